// round 1
// baseline (speedup 1.0000x reference)
#include <cuda_runtime.h>
#include <cuda_bf16.h>

// BilateralGridCP4D: per-point fused eval.
//   gray = tanh(2 * MLP(rgb))           (3 -> 8 relu -> 1)
//   coef[r] = lerp(fac1,x) * lerp(fac2,y) * lerp(fac3,z) * lerp(fac4,gray)
//   out[j]  = sum_r coef[r] * fac0[j][r]   (12 outputs per point)
// Memory-bound: 24 B in + 48 B out per point.

#define RANK 5
#define THREADS 256

__device__ __forceinline__ void interp_mul(const float* __restrict__ fac, int D,
                                           float v, float coef[RANK], bool first)
{
    float pos = (v + 1.0f) * 0.5f * (float)(D - 1);
    pos = fminf(fmaxf(pos, 0.0f), (float)(D - 1));
    float f = floorf(pos);
    int i0 = (int)f;
    if (i0 > D - 2) i0 = D - 2;
    float w = pos - (float)i0;
#pragma unroll
    for (int r = 0; r < RANK; r++) {
        float f0 = fac[r * D + i0];
        float f1 = fac[r * D + i0 + 1];
        float val = fmaf(w, f1 - f0, f0);   // f0*(1-w) + f1*w
        if (first) coef[r] = val;
        else       coef[r] *= val;
    }
}

__global__ __launch_bounds__(THREADS)
void bgrid_cp4d_kernel(const float4* __restrict__ xyz4,
                       const float4* __restrict__ rgb4,
                       const float*  __restrict__ fac0,  // (12,5)
                       const float*  __restrict__ fac1,  // (5,8)
                       const float*  __restrict__ fac2,  // (5,16)
                       const float*  __restrict__ fac3,  // (5,16)
                       const float*  __restrict__ fac4,  // (5,16)
                       const float*  __restrict__ w1,    // (8,3)
                       const float*  __restrict__ b1,    // (8,)
                       const float*  __restrict__ w2,    // (1,8)
                       const float*  __restrict__ b2,    // (1,)
                       float4* __restrict__ out4,        // N*3 float4
                       int nquad)                         // N/4
{
    __shared__ float s_fac0[60];
    __shared__ float s_fac1[40];
    __shared__ float s_fac2[80];
    __shared__ float s_fac3[80];
    __shared__ float s_fac4[80];
    __shared__ float s_w1[24];
    __shared__ float s_b1[8];
    __shared__ float s_w2[8];
    __shared__ float s_b2;

    int tid = threadIdx.x;
    if (tid < 60) s_fac0[tid] = fac0[tid];
    if (tid < 40) s_fac1[tid] = fac1[tid];
    if (tid < 80) s_fac2[tid] = fac2[tid];
    else if (tid < 160) s_fac3[tid - 80] = fac3[tid - 80];
    if (tid >= 160 && tid < 240) s_fac4[tid - 160] = fac4[tid - 160];
    if (tid < 24) { s_w1[tid] = w1[tid]; }
    if (tid >= 24 && tid < 32) s_b1[tid - 24] = b1[tid - 24];
    if (tid >= 32 && tid < 40) s_w2[tid - 32] = w2[tid - 32];
    if (tid == 40) s_b2 = b2[0];
    __syncthreads();

    int t = blockIdx.x * THREADS + tid;
    if (t >= nquad) return;

    // 4 points per thread: 48 B of xyz, 48 B of rgb, each as 3 aligned float4
    float4 a0 = xyz4[3 * t + 0];
    float4 a1 = xyz4[3 * t + 1];
    float4 a2 = xyz4[3 * t + 2];
    float4 c0 = rgb4[3 * t + 0];
    float4 c1 = rgb4[3 * t + 1];
    float4 c2 = rgb4[3 * t + 2];

    float px[4] = {a0.x, a0.w, a1.z, a2.y};
    float py[4] = {a0.y, a1.x, a1.w, a2.z};
    float pz[4] = {a0.z, a1.y, a2.x, a2.w};
    float cr[4] = {c0.x, c0.w, c1.z, c2.y};
    float cg[4] = {c0.y, c1.x, c1.w, c2.z};
    float cb[4] = {c0.z, c1.y, c2.x, c2.w};

#pragma unroll
    for (int p = 0; p < 4; p++) {
        // ---- rgb -> gray MLP ----
        float acc = s_b2;
#pragma unroll
        for (int h = 0; h < 8; h++) {
            float hv = fmaf(s_w1[h * 3 + 0], cr[p],
                       fmaf(s_w1[h * 3 + 1], cg[p],
                       fmaf(s_w1[h * 3 + 2], cb[p], s_b1[h])));
            hv = fmaxf(hv, 0.0f);
            acc = fmaf(s_w2[h], hv, acc);
        }
        float gray = tanhf(2.0f * acc);

        // ---- CP factor products (coords normalized by BOUND=2) ----
        float coef[RANK];
        interp_mul(s_fac1, 8,  px[p] * 0.5f, coef, true);
        interp_mul(s_fac2, 16, py[p] * 0.5f, coef, false);
        interp_mul(s_fac3, 16, pz[p] * 0.5f, coef, false);
        interp_mul(s_fac4, 16, gray,         coef, false);

        // ---- 5 -> 12 linear, 12 floats = 3 float4 ----
        float o[12];
#pragma unroll
        for (int j = 0; j < 12; j++) {
            float s = coef[0] * s_fac0[j * RANK + 0];
#pragma unroll
            for (int r = 1; r < RANK; r++)
                s = fmaf(coef[r], s_fac0[j * RANK + r], s);
            o[j] = s;
        }
        int base = (4 * t + p) * 3;
        out4[base + 0] = make_float4(o[0], o[1], o[2],  o[3]);
        out4[base + 1] = make_float4(o[4], o[5], o[6],  o[7]);
        out4[base + 2] = make_float4(o[8], o[9], o[10], o[11]);
    }
}

extern "C" void kernel_launch(void* const* d_in, const int* in_sizes, int n_in,
                              void* d_out, int out_size)
{
    const float4* xyz4 = (const float4*)d_in[0];
    const float4* rgb4 = (const float4*)d_in[1];
    const float*  fac0 = (const float*)d_in[2];
    const float*  fac1 = (const float*)d_in[3];
    const float*  fac2 = (const float*)d_in[4];
    const float*  fac3 = (const float*)d_in[5];
    const float*  fac4 = (const float*)d_in[6];
    const float*  w1   = (const float*)d_in[7];
    const float*  b1   = (const float*)d_in[8];
    const float*  w2   = (const float*)d_in[9];
    const float*  b2   = (const float*)d_in[10];
    float4* out4 = (float4*)d_out;

    int npts  = in_sizes[0] / 3;   // N
    int nquad = npts / 4;          // N divisible by 4 (N = 2^22)
    int blocks = (nquad + THREADS - 1) / THREADS;
    bgrid_cp4d_kernel<<<blocks, THREADS>>>(xyz4, rgb4, fac0, fac1, fac2, fac3, fac4,
                                           w1, b1, w2, b2, out4, nquad);
}

// round 2
// speedup vs baseline: 1.1431x; 1.1431x over previous
#include <cuda_runtime.h>
#include <cuda_bf16.h>

// BilateralGridCP4D: per-point fused eval, 1 point/thread for occupancy.
//   gray = tanh(2 * MLP(rgb))           (3 -> 8 relu -> 1)
//   coef[r] = lerp(fac1,x) * lerp(fac2,y) * lerp(fac3,z) * lerp(fac4,gray)
//   out[j]  = sum_r coef[r] * fac0[j][r]   (12 outputs per point)
// Memory-bound: 24 B in + 48 B out per point. Latency hiding via occupancy.

#define RANK 5
#define THREADS 256

__device__ __forceinline__ void interp_mul(const float* __restrict__ fac, int D,
                                           float v, float coef[RANK], bool first)
{
    float pos = (v + 1.0f) * 0.5f * (float)(D - 1);
    pos = fminf(fmaxf(pos, 0.0f), (float)(D - 1));
    int i0 = (int)pos;
    if (i0 > D - 2) i0 = D - 2;
    float w = pos - (float)i0;
#pragma unroll
    for (int r = 0; r < RANK; r++) {
        float f0 = fac[r * D + i0];
        float f1 = fac[r * D + i0 + 1];
        float val = fmaf(w, f1 - f0, f0);   // f0*(1-w) + f1*w
        if (first) coef[r] = val;
        else       coef[r] *= val;
    }
}

// tanh(2a) = 1 - 2/(exp(4a)+1), via MUFU ex2. Rel err ~1e-6, no libm slow path.
__device__ __forceinline__ float fast_tanh2(float a)
{
    float e = __expf(4.0f * a);          // +inf for large a -> result 1
    return 1.0f - __fdividef(2.0f, e + 1.0f);  // a << 0: e->0 -> result -1
}

__global__ __launch_bounds__(THREADS)
void bgrid_cp4d_kernel(const float* __restrict__ xyz,
                       const float* __restrict__ rgb,
                       const float* __restrict__ fac0,  // (12,5)
                       const float* __restrict__ fac1,  // (5,8)
                       const float* __restrict__ fac2,  // (5,16)
                       const float* __restrict__ fac3,  // (5,16)
                       const float* __restrict__ fac4,  // (5,16)
                       const float* __restrict__ w1,    // (8,3)
                       const float* __restrict__ b1,    // (8,)
                       const float* __restrict__ w2,    // (1,8)
                       const float* __restrict__ b2,    // (1,)
                       float4* __restrict__ out4,       // N*3 float4
                       int npts)
{
    __shared__ float s_fac0[60];
    __shared__ float s_fac1[40];
    __shared__ float s_fac2[80];
    __shared__ float s_fac3[80];
    __shared__ float s_fac4[80];
    __shared__ float s_w1[24];
    __shared__ float s_b1[8];
    __shared__ float s_w2[8];
    __shared__ float s_b2;

    int tid = threadIdx.x;
    if (tid < 60) s_fac0[tid] = fac0[tid];
    if (tid < 40) s_fac1[tid] = fac1[tid];
    if (tid < 80) s_fac2[tid] = fac2[tid];
    else if (tid < 160) s_fac3[tid - 80] = fac3[tid - 80];
    if (tid >= 160 && tid < 240) s_fac4[tid - 160] = fac4[tid - 160];
    if (tid < 24) s_w1[tid] = w1[tid];
    if (tid >= 24 && tid < 32) s_b1[tid - 24] = b1[tid - 24];
    if (tid >= 32 && tid < 40) s_w2[tid - 32] = w2[tid - 32];
    if (tid == 40) s_b2 = b2[0];
    __syncthreads();

    int i = blockIdx.x * THREADS + tid;
    if (i >= npts) return;

    // 6 scalar coalesced loads (warp covers 384 contiguous bytes per array)
    float x  = xyz[3 * i + 0];
    float y  = xyz[3 * i + 1];
    float z  = xyz[3 * i + 2];
    float r0 = rgb[3 * i + 0];
    float g0 = rgb[3 * i + 1];
    float b0 = rgb[3 * i + 2];

    // ---- rgb -> gray MLP ----
    float acc = s_b2;
#pragma unroll
    for (int h = 0; h < 8; h++) {
        float hv = fmaf(s_w1[h * 3 + 0], r0,
                   fmaf(s_w1[h * 3 + 1], g0,
                   fmaf(s_w1[h * 3 + 2], b0, s_b1[h])));
        hv = fmaxf(hv, 0.0f);
        acc = fmaf(s_w2[h], hv, acc);
    }
    float gray = fast_tanh2(acc);

    // ---- CP factor products (coords normalized by BOUND=2) ----
    float coef[RANK];
    interp_mul(s_fac1, 8,  x * 0.5f, coef, true);
    interp_mul(s_fac2, 16, y * 0.5f, coef, false);
    interp_mul(s_fac3, 16, z * 0.5f, coef, false);
    interp_mul(s_fac4, 16, gray,     coef, false);

    // ---- 5 -> 12 linear, stored as 3 float4 (compute 4, store, repeat) ----
    int base = 3 * i;
#pragma unroll
    for (int q = 0; q < 3; q++) {
        float o[4];
#pragma unroll
        for (int jj = 0; jj < 4; jj++) {
            int j = q * 4 + jj;
            float s = coef[0] * s_fac0[j * RANK + 0];
#pragma unroll
            for (int r = 1; r < RANK; r++)
                s = fmaf(coef[r], s_fac0[j * RANK + r], s);
            o[jj] = s;
        }
        out4[base + q] = make_float4(o[0], o[1], o[2], o[3]);
    }
}

extern "C" void kernel_launch(void* const* d_in, const int* in_sizes, int n_in,
                              void* d_out, int out_size)
{
    const float* xyz  = (const float*)d_in[0];
    const float* rgb  = (const float*)d_in[1];
    const float* fac0 = (const float*)d_in[2];
    const float* fac1 = (const float*)d_in[3];
    const float* fac2 = (const float*)d_in[4];
    const float* fac3 = (const float*)d_in[5];
    const float* fac4 = (const float*)d_in[6];
    const float* w1   = (const float*)d_in[7];
    const float* b1   = (const float*)d_in[8];
    const float* w2   = (const float*)d_in[9];
    const float* b2   = (const float*)d_in[10];
    float4* out4 = (float4*)d_out;

    int npts = in_sizes[0] / 3;    // N
    int blocks = (npts + THREADS - 1) / THREADS;
    bgrid_cp4d_kernel<<<blocks, THREADS>>>(xyz, rgb, fac0, fac1, fac2, fac3, fac4,
                                           w1, b1, w2, b2, out4, npts);
}